// round 1
// baseline (speedup 1.0000x reference)
#include <cuda_runtime.h>
#include <cuda_bf16.h>
#include <float.h>

#define NSAMP   100
#define IMG_W   2048
#define IMG_H   2048
#define WM1     2047.0f
#define TPB     256
#define MAXBLK  1024

__device__ float g_partials[MAXBLK];

__device__ __forceinline__ float bilin(const float* __restrict__ img, float x, float y) {
    // x, y already clamped to [0, 2047]
    float x0 = floorf(x), y0 = floorf(y);
    float wx = x - x0,    wy = y - y0;
    int x0i = (int)x0;
    int y0i = (int)y0;
    int x1i = min(x0i + 1, IMG_W - 1);
    int y1i = min(y0i + 1, IMG_H - 1);
    const float* r0 = img + y0i * IMG_W;
    const float* r1 = img + y1i * IMG_W;
    float a = __ldg(r0 + x0i);
    float b = __ldg(r0 + x1i);
    float c = __ldg(r1 + x0i);
    float d = __ldg(r1 + x1i);
    float omwx = 1.0f - wx;
    float top = a * omwx + b * wx;
    float bot = c * omwx + d * wx;
    return top * (1.0f - wy) + bot * wy;
}

__global__ void __launch_bounds__(TPB)
contour_loss_kernel(const float* __restrict__ img,
                    const float* __restrict__ points,
                    const float* __restrict__ normals,
                    int N) {
    int i = blockIdx.x * blockDim.x + threadIdx.x;
    float sq = 0.0f;

    if (i < N) {
        float px = fminf(fmaxf(points[2 * i],     0.0f), WM1);
        float py = fminf(fmaxf(points[2 * i + 1], 0.0f), WM1);
        float nx = normals[2 * i];
        float ny = normals[2 * i + 1];
        // d = perpendicular of normal, normalized
        float dx = -ny, dy = nx;
        float inv = rsqrtf(dx * dx + dy * dy);
        dx *= inv; dy *= inv;

        float t_left  = (dx != 0.0f) ? (0.0f - px) / dx : -FLT_MAX;
        float t_right = (dx != 0.0f) ? (WM1  - px) / dx :  FLT_MAX;
        float t_top   = (dy != 0.0f) ? (0.0f - py) / dy : -FLT_MAX;
        float t_bot   = (dy != 0.0f) ? (WM1  - py) / dy :  FLT_MAX;
        float t_min = fmaxf(t_left,  t_top);
        float t_max = fminf(t_right, t_bot);

        float p1x = fmaf(t_min, dx, px), p1y = fmaf(t_min, dy, py);
        float p2x = fmaf(t_max, dx, px), p2y = fmaf(t_max, dy, py);
        float vx = p2x - p1x, vy = p2y - p1y;

        float ref_val = bilin(img, px, py);

        const float step = 1.0f / 99.0f;

        // sample 0 (t = 0)
        float lx = fminf(fmaxf(p1x, 0.0f), WM1);
        float ly = fminf(fmaxf(p1y, 0.0f), WM1);
        float v_prev = bilin(img, lx, ly);

        // sample 1 (t = 1/99)
        lx = fminf(fmaxf(fmaf(step, vx, p1x), 0.0f), WM1);
        ly = fminf(fmaxf(fmaf(step, vy, p1y), 0.0f), WM1);
        float v_cur = bilin(img, lx, ly);
        float cx = lx, cy = ly;

        // argmin over all-inf dist -> index 0 -> vals[1]
        float best_val  = v_cur;
        float best_dist = FLT_MAX;

        #pragma unroll 4
        for (int s = 1; s <= 98; s++) {
            float tn  = (float)(s + 1) * step;
            float nlx = fminf(fmaxf(fmaf(tn, vx, p1x), 0.0f), WM1);
            float nly = fminf(fmaxf(fmaf(tn, vy, p1y), 0.0f), WM1);
            float v_next = bilin(img, nlx, nly);

            if (v_cur < v_prev && v_cur < v_next) {
                float ddx = cx - px, ddy = cy - py;
                float dist = sqrtf(ddx * ddx + ddy * ddy);
                if (dist < best_dist) {    // strict < keeps FIRST minimum (argmin semantics)
                    best_dist = dist;
                    best_val  = v_cur;
                }
            }
            v_prev = v_cur;
            v_cur  = v_next;
            cx = nlx; cy = nly;
        }

        float diff = best_val - ref_val;
        sq = diff * diff;
    }

    // block reduction (deterministic within a block)
    __shared__ float smem[TPB / 32];
    float v = sq;
    #pragma unroll
    for (int off = 16; off > 0; off >>= 1)
        v += __shfl_down_sync(0xFFFFFFFFu, v, off);
    int lane = threadIdx.x & 31;
    int wid  = threadIdx.x >> 5;
    if (lane == 0) smem[wid] = v;
    __syncthreads();
    if (wid == 0) {
        v = (lane < TPB / 32) ? smem[lane] : 0.0f;
        #pragma unroll
        for (int off = 4; off > 0; off >>= 1)
            v += __shfl_down_sync(0xFFFFFFFFu, v, off);
        if (lane == 0) g_partials[blockIdx.x] = v;
    }
}

__global__ void __launch_bounds__(TPB)
final_reduce_kernel(float* __restrict__ out, int nblocks, float inv_n) {
    float v = 0.0f;
    for (int i = threadIdx.x; i < nblocks; i += TPB)
        v += g_partials[i];
    __shared__ float smem[TPB / 32];
    #pragma unroll
    for (int off = 16; off > 0; off >>= 1)
        v += __shfl_down_sync(0xFFFFFFFFu, v, off);
    int lane = threadIdx.x & 31;
    int wid  = threadIdx.x >> 5;
    if (lane == 0) smem[wid] = v;
    __syncthreads();
    if (wid == 0) {
        v = (lane < TPB / 32) ? smem[lane] : 0.0f;
        #pragma unroll
        for (int off = 4; off > 0; off >>= 1)
            v += __shfl_down_sync(0xFFFFFFFFu, v, off);
        if (lane == 0) out[0] = v * inv_n;
    }
}

extern "C" void kernel_launch(void* const* d_in, const int* in_sizes, int n_in,
                              void* d_out, int out_size) {
    const float* img     = (const float*)d_in[0];  // (2048, 2048) fp32
    const float* points  = (const float*)d_in[1];  // (N, 2)      fp32
    const float* normals = (const float*)d_in[2];  // (N, 2)      fp32
    float* out = (float*)d_out;

    int N = in_sizes[1] / 2;
    int blocks = (N + TPB - 1) / TPB;

    contour_loss_kernel<<<blocks, TPB>>>(img, points, normals, N);
    final_reduce_kernel<<<1, TPB>>>(out, blocks, 1.0f / (float)N);
}

// round 2
// speedup vs baseline: 1.0660x; 1.0660x over previous
#include <cuda_runtime.h>
#include <cuda_bf16.h>
#include <float.h>

#define IMG_W   2048
#define IMG_H   2048
#define WM1     2047.0f
#define TPB     128
#define BUILD_TPB 256
#define MAXBLK  2048

// Quad table: tab[y*2048+x] = {img[y][x], img[y][x1], img[y1][x], img[y1][x1]}
// with x1=min(x+1,2047), y1=min(y+1,2047). One 16B-aligned load per bilinear.
__device__ float4 g_tab[IMG_W * IMG_H];          // 64 MB, fits in L2 alongside image
__device__ float g_partials[MAXBLK];
__device__ unsigned int g_count;                 // zero-init; auto-wraps via atomicInc

__global__ void __launch_bounds__(BUILD_TPB)
build_tab_kernel(const float* __restrict__ img) {
    int idx = blockIdx.x * BUILD_TPB + threadIdx.x;
    int y = idx >> 11;
    int x = idx & (IMG_W - 1);
    int x1 = min(x + 1, IMG_W - 1);
    const float* r0 = img + y * IMG_W;
    const float* r1 = img + min(y + 1, IMG_H - 1) * IMG_W;
    g_tab[idx] = make_float4(__ldg(r0 + x), __ldg(r0 + x1),
                             __ldg(r1 + x), __ldg(r1 + x1));
}

__device__ __forceinline__ float bilin_tab(float x, float y) {
    // x, y already clamped to [0, 2047]
    float x0 = floorf(x), y0 = floorf(y);
    float wx = x - x0,    wy = y - y0;
    int xi = (int)x0, yi = (int)y0;
    float4 q = __ldg(&g_tab[yi * IMG_W + xi]);
    float omwx = 1.0f - wx;
    float top = q.x * omwx + q.y * wx;
    float bot = q.z * omwx + q.w * wx;
    return top * (1.0f - wy) + bot * wy;
}

__global__ void __launch_bounds__(TPB)
contour_loss_kernel(const float* __restrict__ points,
                    const float* __restrict__ normals,
                    float* __restrict__ out,
                    int N, int nblocks, float inv_n) {
    int i = blockIdx.x * TPB + threadIdx.x;
    float sq = 0.0f;

    if (i < N) {
        float px = fminf(fmaxf(points[2 * i],     0.0f), WM1);
        float py = fminf(fmaxf(points[2 * i + 1], 0.0f), WM1);
        float nx = normals[2 * i];
        float ny = normals[2 * i + 1];
        float dx = -ny, dy = nx;
        float inv = rsqrtf(dx * dx + dy * dy);
        dx *= inv; dy *= inv;

        float t_left  = (dx != 0.0f) ? (0.0f - px) / dx : -FLT_MAX;
        float t_right = (dx != 0.0f) ? (WM1  - px) / dx :  FLT_MAX;
        float t_top   = (dy != 0.0f) ? (0.0f - py) / dy : -FLT_MAX;
        float t_bot   = (dy != 0.0f) ? (WM1  - py) / dy :  FLT_MAX;
        float t_min = fmaxf(t_left,  t_top);
        float t_max = fminf(t_right, t_bot);

        float p1x = fmaf(t_min, dx, px), p1y = fmaf(t_min, dy, py);
        float p2x = fmaf(t_max, dx, px), p2y = fmaf(t_max, dy, py);
        float vx = p2x - p1x, vy = p2y - p1y;

        float ref_val = bilin_tab(px, py);

        const float step = 1.0f / 99.0f;

        // sample 0 (t = 0)
        float lx = fminf(fmaxf(p1x, 0.0f), WM1);
        float ly = fminf(fmaxf(p1y, 0.0f), WM1);
        float v_prev = bilin_tab(lx, ly);

        // sample 1 (t = 1/99)
        lx = fminf(fmaxf(fmaf(step, vx, p1x), 0.0f), WM1);
        ly = fminf(fmaxf(fmaf(step, vy, p1y), 0.0f), WM1);
        float v_cur = bilin_tab(lx, ly);
        float cx = lx, cy = ly;

        // argmin over all-inf dist -> index 0 -> vals[1]
        float best_val  = v_cur;
        float best_dist = FLT_MAX;

        #pragma unroll 7
        for (int s = 1; s <= 98; s++) {
            float tn  = (float)(s + 1) * step;
            float nlx = fminf(fmaxf(fmaf(tn, vx, p1x), 0.0f), WM1);
            float nly = fminf(fmaxf(fmaf(tn, vy, p1y), 0.0f), WM1);
            float v_next = bilin_tab(nlx, nly);

            if (v_cur < v_prev && v_cur < v_next) {
                float ddx = cx - px, ddy = cy - py;
                float dist = sqrtf(ddx * ddx + ddy * ddy);
                if (dist < best_dist) {   // strict < keeps FIRST minimum
                    best_dist = dist;
                    best_val  = v_cur;
                }
            }
            v_prev = v_cur;
            v_cur  = v_next;
            cx = nlx; cy = nly;
        }

        float diff = best_val - ref_val;
        sq = diff * diff;
    }

    // ── block reduction (deterministic within a block) ──
    __shared__ float smem[TPB / 32];
    __shared__ bool s_last;
    float v = sq;
    #pragma unroll
    for (int off = 16; off > 0; off >>= 1)
        v += __shfl_down_sync(0xFFFFFFFFu, v, off);
    int lane = threadIdx.x & 31;
    int wid  = threadIdx.x >> 5;
    if (lane == 0) smem[wid] = v;
    __syncthreads();
    if (wid == 0) {
        v = (lane < TPB / 32) ? smem[lane] : 0.0f;
        #pragma unroll
        for (int off = 2; off > 0; off >>= 1)
            v += __shfl_down_sync(0xFFFFFFFFu, v, off);
        if (lane == 0) {
            g_partials[blockIdx.x] = v;
            __threadfence();
            // atomicInc wraps to 0 after nblocks increments -> auto-reset
            unsigned int t = atomicInc(&g_count, (unsigned int)(nblocks - 1));
            s_last = (t == (unsigned int)(nblocks - 1));
        }
    }
    __syncthreads();

    // ── last block sums all partials (fixed strided order => deterministic) ──
    if (s_last) {
        float acc = 0.0f;
        for (int k = threadIdx.x; k < nblocks; k += TPB)
            acc += g_partials[k];
        #pragma unroll
        for (int off = 16; off > 0; off >>= 1)
            acc += __shfl_down_sync(0xFFFFFFFFu, acc, off);
        if (lane == 0) smem[wid] = acc;
        __syncthreads();
        if (wid == 0) {
            acc = (lane < TPB / 32) ? smem[lane] : 0.0f;
            #pragma unroll
            for (int off = 2; off > 0; off >>= 1)
                acc += __shfl_down_sync(0xFFFFFFFFu, acc, off);
            if (lane == 0) out[0] = acc * inv_n;
        }
    }
}

extern "C" void kernel_launch(void* const* d_in, const int* in_sizes, int n_in,
                              void* d_out, int out_size) {
    const float* img     = (const float*)d_in[0];  // (2048, 2048) fp32
    const float* points  = (const float*)d_in[1];  // (N, 2)      fp32
    const float* normals = (const float*)d_in[2];  // (N, 2)      fp32
    float* out = (float*)d_out;

    int N = in_sizes[1] / 2;
    int blocks = (N + TPB - 1) / TPB;

    build_tab_kernel<<<(IMG_W * IMG_H) / BUILD_TPB, BUILD_TPB>>>(img);
    contour_loss_kernel<<<blocks, TPB>>>(points, normals, out, N, blocks,
                                         1.0f / (float)N);
}

// round 3
// speedup vs baseline: 1.2772x; 1.1982x over previous
#include <cuda_runtime.h>
#include <cuda_bf16.h>
#include <float.h>

#define IMG_W   2048
#define IMG_H   2048
#define WM1     2047.0f
#define TPB     128
#define BUILD_TPB 256
#define MAXBLK  4096
#define SPLIT   4          // threads per point

// Quad table: tab[y*2048+x] = {img[y][x], img[y][x1], img[y1][x], img[y1][x1]}
__device__ float4 g_tab[IMG_W * IMG_H];          // 64 MB, L2-resident
__device__ float g_partials[MAXBLK];
__device__ unsigned int g_count;                 // zero-init; wraps via atomicInc

__global__ void __launch_bounds__(BUILD_TPB)
build_tab_kernel(const float* __restrict__ img) {
    int idx = blockIdx.x * BUILD_TPB + threadIdx.x;
    int y = idx >> 11;
    int x = idx & (IMG_W - 1);
    int x1 = min(x + 1, IMG_W - 1);
    const float* r0 = img + y * IMG_W;
    const float* r1 = img + min(y + 1, IMG_H - 1) * IMG_W;
    g_tab[idx] = make_float4(__ldg(r0 + x), __ldg(r0 + x1),
                             __ldg(r1 + x), __ldg(r1 + x1));
}

__device__ __forceinline__ float bilin_tab(float x, float y) {
    float x0 = floorf(x), y0 = floorf(y);
    float wx = x - x0,    wy = y - y0;
    int xi = (int)x0, yi = (int)y0;
    float4 q = __ldg(&g_tab[yi * IMG_W + xi]);
    float omwx = 1.0f - wx;
    float top = q.x * omwx + q.y * wx;
    float bot = q.z * omwx + q.w * wx;
    return top * (1.0f - wy) + bot * wy;
}

__global__ void __launch_bounds__(TPB)
contour_loss_kernel(const float* __restrict__ points,
                    const float* __restrict__ normals,
                    float* __restrict__ out,
                    int N, int nblocks, float inv_n) {
    int gtid = blockIdx.x * TPB + threadIdx.x;
    int pt  = gtid >> 2;        // point index
    int sub = gtid & 3;         // segment index within point
    float sq = 0.0f;

    if (pt < N) {
        float px = fminf(fmaxf(__ldg(&points[2 * pt]),     0.0f), WM1);
        float py = fminf(fmaxf(__ldg(&points[2 * pt + 1]), 0.0f), WM1);
        float nx = __ldg(&normals[2 * pt]);
        float ny = __ldg(&normals[2 * pt + 1]);
        float dx = -ny, dy = nx;
        float inv = rsqrtf(dx * dx + dy * dy);
        dx *= inv; dy *= inv;

        float t_left  = (dx != 0.0f) ? (0.0f - px) / dx : -FLT_MAX;
        float t_right = (dx != 0.0f) ? (WM1  - px) / dx :  FLT_MAX;
        float t_top   = (dy != 0.0f) ? (0.0f - py) / dy : -FLT_MAX;
        float t_bot   = (dy != 0.0f) ? (WM1  - py) / dy :  FLT_MAX;
        float t_min = fmaxf(t_left,  t_top);
        float t_max = fminf(t_right, t_bot);

        float p1x = fmaf(t_min, dx, px), p1y = fmaf(t_min, dy, py);
        float p2x = fmaf(t_max, dx, px), p2y = fmaf(t_max, dy, py);
        float vx = p2x - p1x, vy = p2y - p1y;

        const float step = 1.0f / 99.0f;

        // centers this thread owns: [c_lo, c_hi]; needs samples [c_lo-1, c_hi+1]
        int c_lo = 1 + sub * 25;
        int c_hi = min(c_lo + 24, 98);

        // samples c_lo-1 and c_lo
        float t0 = (float)(c_lo - 1) * step;
        float lx = fminf(fmaxf(fmaf(t0, vx, p1x), 0.0f), WM1);
        float ly = fminf(fmaxf(fmaf(t0, vy, p1y), 0.0f), WM1);
        float v_prev = bilin_tab(lx, ly);

        float t1 = (float)c_lo * step;
        lx = fminf(fmaxf(fmaf(t1, vx, p1x), 0.0f), WM1);
        ly = fminf(fmaxf(fmaf(t1, vy, p1y), 0.0f), WM1);
        float v_cur = bilin_tab(lx, ly);
        float cx = lx, cy = ly;

        // defaults: sub 0 carries vals[1] (argmin of all-inf -> idx 0 -> vals[1])
        float best_dist = FLT_MAX;
        int   best_idx  = (sub == 0) ? 0x7FFFFFFE : 0x7FFFFFFF;
        float best_val  = (sub == 0) ? v_cur : 0.0f;

        #pragma unroll 5
        for (int s = c_lo; s <= c_hi; s++) {
            float tn  = (float)(s + 1) * step;
            float nlx = fminf(fmaxf(fmaf(tn, vx, p1x), 0.0f), WM1);
            float nly = fminf(fmaxf(fmaf(tn, vy, p1y), 0.0f), WM1);
            float v_next = bilin_tab(nlx, nly);

            if (v_cur < v_prev && v_cur < v_next) {
                float ddx = cx - px, ddy = cy - py;
                float dist = sqrtf(ddx * ddx + ddy * ddy);
                if (dist < best_dist) {   // ascending s + strict < = first minimum
                    best_dist = dist;
                    best_idx  = s;
                    best_val  = v_cur;
                }
            }
            v_prev = v_cur;
            v_cur  = v_next;
            cx = nlx; cy = nly;
        }

        // combine across the 4 sub-threads (lexicographic on (dist, idx))
        #pragma unroll
        for (int m = 1; m <= 2; m <<= 1) {
            float od = __shfl_xor_sync(0xFFFFFFFFu, best_dist, m);
            int   oi = __shfl_xor_sync(0xFFFFFFFFu, best_idx,  m);
            float ov = __shfl_xor_sync(0xFFFFFFFFu, best_val,  m);
            if (od < best_dist || (od == best_dist && oi < best_idx)) {
                best_dist = od; best_idx = oi; best_val = ov;
            }
        }

        if (sub == 0) {
            float ref_val = bilin_tab(px, py);
            float diff = best_val - ref_val;
            sq = diff * diff;
        }
    }

    // ── block reduction (deterministic) ──
    __shared__ float smem[TPB / 32];
    __shared__ bool s_last;
    float v = sq;
    #pragma unroll
    for (int off = 16; off > 0; off >>= 1)
        v += __shfl_down_sync(0xFFFFFFFFu, v, off);
    int lane = threadIdx.x & 31;
    int wid  = threadIdx.x >> 5;
    if (lane == 0) smem[wid] = v;
    __syncthreads();
    if (wid == 0) {
        v = (lane < TPB / 32) ? smem[lane] : 0.0f;
        #pragma unroll
        for (int off = 2; off > 0; off >>= 1)
            v += __shfl_down_sync(0xFFFFFFFFu, v, off);
        if (lane == 0) {
            g_partials[blockIdx.x] = v;
            __threadfence();
            unsigned int t = atomicInc(&g_count, (unsigned int)(nblocks - 1));
            s_last = (t == (unsigned int)(nblocks - 1));
        }
    }
    __syncthreads();

    // ── last block sums partials (fixed strided order => deterministic) ──
    if (s_last) {
        float acc = 0.0f;
        for (int k = threadIdx.x; k < nblocks; k += TPB)
            acc += g_partials[k];
        #pragma unroll
        for (int off = 16; off > 0; off >>= 1)
            acc += __shfl_down_sync(0xFFFFFFFFu, acc, off);
        if (lane == 0) smem[wid] = acc;
        __syncthreads();
        if (wid == 0) {
            acc = (lane < TPB / 32) ? smem[lane] : 0.0f;
            #pragma unroll
            for (int off = 2; off > 0; off >>= 1)
                acc += __shfl_down_sync(0xFFFFFFFFu, acc, off);
            if (lane == 0) out[0] = acc * inv_n;
        }
    }
}

extern "C" void kernel_launch(void* const* d_in, const int* in_sizes, int n_in,
                              void* d_out, int out_size) {
    const float* img     = (const float*)d_in[0];
    const float* points  = (const float*)d_in[1];
    const float* normals = (const float*)d_in[2];
    float* out = (float*)d_out;

    int N = in_sizes[1] / 2;
    int total = N * SPLIT;
    int blocks = (total + TPB - 1) / TPB;

    build_tab_kernel<<<(IMG_W * IMG_H) / BUILD_TPB, BUILD_TPB>>>(img);
    contour_loss_kernel<<<blocks, TPB>>>(points, normals, out, N, blocks,
                                         1.0f / (float)N);
}